// round 1
// baseline (speedup 1.0000x reference)
#include <cuda_runtime.h>

// Problem constants
#define NB   16
#define SS_  1024
#define DD_  1024
#define MTOT (NB * SS_)            // 16384 rows
#define PLANE (MTOT * DD_)         // 16,777,216 elements per [B,S,D] tensor

// ---------------- scratch (device globals; no allocation allowed) ----------
__device__ float g_qr[PLANE];
__device__ float g_qi[PLANE];
__device__ float g_kr[PLANE];
__device__ float g_ki[PLANE];
__device__ float g_vr[PLANE];
__device__ float g_vi[PLANE];
__device__ float g_att[PLANE];     // [B, S, S]
__device__ float g_or[PLANE];
__device__ float g_oi[PLANE];

struct ProjArgs {
    const float* X[6];
    const float* W[6];
    const float* Bv[6];
};

__device__ __forceinline__ float* proj_dst(int z) {
    switch (z) {
        case 0: return g_qr;
        case 1: return g_qi;
        case 2: return g_kr;
        case 3: return g_ki;
        case 4: return g_vr;
        default: return g_vi;
    }
}

// Tiling: 128x128 block tile, BK=8, 256 threads, 8x8 per-thread microtile.
#define LDP 132   // padded smem row (breaks STS bank conflicts)

// ---------------------------------------------------------------------------
// Projections: C[m,n] = sum_k X[m,k] * W[n,k] + bias[n]   (NT GEMM)
// grid = (8, 128, 6); z selects which projection.
// ---------------------------------------------------------------------------
__global__ __launch_bounds__(256) void proj_kernel(ProjArgs p) {
    const int z = blockIdx.z;
    const float* __restrict__ A = p.X[z];
    const float* __restrict__ W = p.W[z];
    const float* __restrict__ bias = p.Bv[z];
    float* __restrict__ C = proj_dst(z);

    __shared__ __align__(16) float As[8][LDP];
    __shared__ __align__(16) float Bs[8][LDP];

    const int tid = threadIdx.x;
    const int tx = tid & 15, ty = tid >> 4;
    const int arow = tid >> 1, ak4 = (tid & 1) * 4;
    const int m0 = blockIdx.y * 128, n0 = blockIdx.x * 128;

    float acc[8][8] = {};

    for (int k0 = 0; k0 < 1024; k0 += 8) {
        float4 v;
        v = *(const float4*)&A[(m0 + arow) * 1024 + k0 + ak4];
        As[ak4 + 0][arow] = v.x; As[ak4 + 1][arow] = v.y;
        As[ak4 + 2][arow] = v.z; As[ak4 + 3][arow] = v.w;
        v = *(const float4*)&W[(n0 + arow) * 1024 + k0 + ak4];
        Bs[ak4 + 0][arow] = v.x; Bs[ak4 + 1][arow] = v.y;
        Bs[ak4 + 2][arow] = v.z; Bs[ak4 + 3][arow] = v.w;
        __syncthreads();
        #pragma unroll
        for (int kk = 0; kk < 8; kk++) {
            float4 a0 = *(const float4*)&As[kk][ty * 8];
            float4 a1 = *(const float4*)&As[kk][ty * 8 + 4];
            float4 b0 = *(const float4*)&Bs[kk][tx * 8];
            float4 b1 = *(const float4*)&Bs[kk][tx * 8 + 4];
            float a[8] = {a0.x, a0.y, a0.z, a0.w, a1.x, a1.y, a1.z, a1.w};
            float b[8] = {b0.x, b0.y, b0.z, b0.w, b1.x, b1.y, b1.z, b1.w};
            #pragma unroll
            for (int i = 0; i < 8; i++)
                #pragma unroll
                for (int j = 0; j < 8; j++)
                    acc[i][j] += a[i] * b[j];
        }
        __syncthreads();
    }

    #pragma unroll
    for (int i = 0; i < 8; i++) {
        const int m = m0 + ty * 8 + i;
        #pragma unroll
        for (int j = 0; j < 8; j += 4) {
            const int n = n0 + tx * 8 + j;
            float4 o;
            o.x = acc[i][j + 0] + bias[n + 0];
            o.y = acc[i][j + 1] + bias[n + 1];
            o.z = acc[i][j + 2] + bias[n + 2];
            o.w = acc[i][j + 3] + bias[n + 3];
            *(float4*)&C[m * 1024 + n] = o;
        }
    }
}

// ---------------------------------------------------------------------------
// Fused scores: C[b,s,e] = sum_d qr[b,s,d]*kr[b,d,e] + sum_d qi[b,s,d]*ki[b,e,d]
// (NN + NT dual-accumulate). Raw scores written; /8 folded into softmax.
// grid = (8, 8, 16)
// ---------------------------------------------------------------------------
__global__ __launch_bounds__(256) void scores_kernel() {
    const int b = blockIdx.z;
    const float* __restrict__ qr = g_qr + b * (SS_ * DD_);
    const float* __restrict__ qi = g_qi + b * (SS_ * DD_);
    const float* __restrict__ kr = g_kr + b * (SS_ * DD_);
    const float* __restrict__ ki = g_ki + b * (SS_ * DD_);
    float* __restrict__ C = g_att + b * (SS_ * SS_);

    __shared__ __align__(16) float Ar[8][LDP];
    __shared__ __align__(16) float Ai[8][LDP];
    __shared__ __align__(16) float Br[8][LDP];
    __shared__ __align__(16) float Bi[8][LDP];

    const int tid = threadIdx.x;
    const int tx = tid & 15, ty = tid >> 4;
    const int arow = tid >> 1, ak4 = (tid & 1) * 4;
    const int brow = tid >> 5, bn4 = (tid & 31) * 4;
    const int m0 = blockIdx.y * 128, n0 = blockIdx.x * 128;

    float acc[8][8] = {};

    for (int k0 = 0; k0 < 1024; k0 += 8) {
        float4 v;
        v = *(const float4*)&qr[(m0 + arow) * 1024 + k0 + ak4];
        Ar[ak4 + 0][arow] = v.x; Ar[ak4 + 1][arow] = v.y;
        Ar[ak4 + 2][arow] = v.z; Ar[ak4 + 3][arow] = v.w;
        v = *(const float4*)&qi[(m0 + arow) * 1024 + k0 + ak4];
        Ai[ak4 + 0][arow] = v.x; Ai[ak4 + 1][arow] = v.y;
        Ai[ak4 + 2][arow] = v.z; Ai[ak4 + 3][arow] = v.w;
        // kr: NN  (row = contraction dim d)
        v = *(const float4*)&kr[(k0 + brow) * 1024 + n0 + bn4];
        *(float4*)&Br[brow][bn4] = v;
        // ki: NT  (row = output dim t)
        v = *(const float4*)&ki[(n0 + arow) * 1024 + k0 + ak4];
        Bi[ak4 + 0][arow] = v.x; Bi[ak4 + 1][arow] = v.y;
        Bi[ak4 + 2][arow] = v.z; Bi[ak4 + 3][arow] = v.w;
        __syncthreads();
        #pragma unroll
        for (int kk = 0; kk < 8; kk++) {
            float4 t0, t1;
            t0 = *(const float4*)&Ar[kk][ty * 8];
            t1 = *(const float4*)&Ar[kk][ty * 8 + 4];
            float ar[8] = {t0.x, t0.y, t0.z, t0.w, t1.x, t1.y, t1.z, t1.w};
            t0 = *(const float4*)&Ai[kk][ty * 8];
            t1 = *(const float4*)&Ai[kk][ty * 8 + 4];
            float ai[8] = {t0.x, t0.y, t0.z, t0.w, t1.x, t1.y, t1.z, t1.w};
            t0 = *(const float4*)&Br[kk][tx * 8];
            t1 = *(const float4*)&Br[kk][tx * 8 + 4];
            float br[8] = {t0.x, t0.y, t0.z, t0.w, t1.x, t1.y, t1.z, t1.w};
            t0 = *(const float4*)&Bi[kk][tx * 8];
            t1 = *(const float4*)&Bi[kk][tx * 8 + 4];
            float bi[8] = {t0.x, t0.y, t0.z, t0.w, t1.x, t1.y, t1.z, t1.w};
            #pragma unroll
            for (int i = 0; i < 8; i++)
                #pragma unroll
                for (int j = 0; j < 8; j++)
                    acc[i][j] += ar[i] * br[j] + ai[i] * bi[j];
        }
        __syncthreads();
    }

    #pragma unroll
    for (int i = 0; i < 8; i++) {
        const int m = m0 + ty * 8 + i;
        #pragma unroll
        for (int j = 0; j < 8; j += 4) {
            const int n = n0 + tx * 8 + j;
            float4 o = {acc[i][j], acc[i][j + 1], acc[i][j + 2], acc[i][j + 3]};
            *(float4*)&C[m * 1024 + n] = o;
        }
    }
}

// ---------------------------------------------------------------------------
// Softmax over last dim (1024), with the 1/sqrt(64)=0.125 scale folded in.
// grid = 16384 blocks, 256 threads, 4 elems/thread. In-place on g_att.
// ---------------------------------------------------------------------------
__global__ __launch_bounds__(256) void softmax_kernel() {
    __shared__ float red[8];
    float* __restrict__ p = g_att + (size_t)blockIdx.x * 1024;
    const int tid = threadIdx.x;

    float4 v = ((float4*)p)[tid];
    v.x *= 0.125f; v.y *= 0.125f; v.z *= 0.125f; v.w *= 0.125f;

    float m = fmaxf(fmaxf(v.x, v.y), fmaxf(v.z, v.w));
    #pragma unroll
    for (int o = 16; o; o >>= 1) m = fmaxf(m, __shfl_xor_sync(0xffffffffu, m, o));
    if ((tid & 31) == 0) red[tid >> 5] = m;
    __syncthreads();
    float M = red[0];
    #pragma unroll
    for (int i = 1; i < 8; i++) M = fmaxf(M, red[i]);
    __syncthreads();

    v.x = expf(v.x - M); v.y = expf(v.y - M);
    v.z = expf(v.z - M); v.w = expf(v.w - M);
    float s = v.x + v.y + v.z + v.w;
    #pragma unroll
    for (int o = 16; o; o >>= 1) s += __shfl_xor_sync(0xffffffffu, s, o);
    if ((tid & 31) == 0) red[tid >> 5] = s;
    __syncthreads();
    float T = 0.f;
    #pragma unroll
    for (int i = 0; i < 8; i++) T += red[i];

    const float inv = 1.0f / T;
    v.x *= inv; v.y *= inv; v.z *= inv; v.w *= inv;
    ((float4*)p)[tid] = v;
}

// ---------------------------------------------------------------------------
// out = attn @ V   (NN GEMM). grid = (8, 8, 32): z = batch | (which << 4).
// ---------------------------------------------------------------------------
__global__ __launch_bounds__(256) void av_kernel() {
    const int z = blockIdx.z;
    const int b = z & 15;
    const int which = z >> 4;
    const float* __restrict__ A = g_att + b * (SS_ * SS_);
    const float* __restrict__ Bm = (which ? g_vi : g_vr) + b * (SS_ * DD_);
    float* __restrict__ C = (which ? g_oi : g_or) + b * (SS_ * DD_);

    __shared__ __align__(16) float As[8][LDP];
    __shared__ __align__(16) float Bs[8][LDP];

    const int tid = threadIdx.x;
    const int tx = tid & 15, ty = tid >> 4;
    const int arow = tid >> 1, ak4 = (tid & 1) * 4;
    const int brow = tid >> 5, bn4 = (tid & 31) * 4;
    const int m0 = blockIdx.y * 128, n0 = blockIdx.x * 128;

    float acc[8][8] = {};

    for (int k0 = 0; k0 < 1024; k0 += 8) {
        float4 v;
        v = *(const float4*)&A[(m0 + arow) * 1024 + k0 + ak4];
        As[ak4 + 0][arow] = v.x; As[ak4 + 1][arow] = v.y;
        As[ak4 + 2][arow] = v.z; As[ak4 + 3][arow] = v.w;
        v = *(const float4*)&Bm[(k0 + brow) * 1024 + n0 + bn4];
        *(float4*)&Bs[brow][bn4] = v;
        __syncthreads();
        #pragma unroll
        for (int kk = 0; kk < 8; kk++) {
            float4 a0 = *(const float4*)&As[kk][ty * 8];
            float4 a1 = *(const float4*)&As[kk][ty * 8 + 4];
            float4 b0 = *(const float4*)&Bs[kk][tx * 8];
            float4 b1 = *(const float4*)&Bs[kk][tx * 8 + 4];
            float a[8] = {a0.x, a0.y, a0.z, a0.w, a1.x, a1.y, a1.z, a1.w};
            float b[8] = {b0.x, b0.y, b0.z, b0.w, b1.x, b1.y, b1.z, b1.w};
            #pragma unroll
            for (int i = 0; i < 8; i++)
                #pragma unroll
                for (int j = 0; j < 8; j++)
                    acc[i][j] += a[i] * b[j];
        }
        __syncthreads();
    }

    #pragma unroll
    for (int i = 0; i < 8; i++) {
        const int m = m0 + ty * 8 + i;
        #pragma unroll
        for (int j = 0; j < 8; j += 4) {
            const int n = n0 + tx * 8 + j;
            float4 o = {acc[i][j], acc[i][j + 1], acc[i][j + 2], acc[i][j + 3]};
            *(float4*)&C[m * 1024 + n] = o;
        }
    }
}

// ---------------------------------------------------------------------------
// Complex LayerNorm over D=1024 + output writeback.
// z = out_r + i*out_i; mean/var in complex arithmetic; std = complex sqrt;
// y = a2 * (z-mean)/std + b2 (b2 real-only). Output [2,B,S,D].
// grid = 16384 blocks, 256 threads.
// ---------------------------------------------------------------------------
__global__ __launch_bounds__(256) void lnorm_kernel(const float* __restrict__ a2,
                                                    const float* __restrict__ b2,
                                                    float* __restrict__ out) {
    __shared__ float red[5][8];
    const size_t row = blockIdx.x;
    const int tid = threadIdx.x;
    const float4 ar = ((const float4*)(g_or + row * 1024))[tid];
    const float4 ai = ((const float4*)(g_oi + row * 1024))[tid];

    float sr  = ar.x + ar.y + ar.z + ar.w;
    float si  = ai.x + ai.y + ai.z + ai.w;
    float srr = ar.x * ar.x + ar.y * ar.y + ar.z * ar.z + ar.w * ar.w;
    float sii = ai.x * ai.x + ai.y * ai.y + ai.z * ai.z + ai.w * ai.w;
    float sri = ar.x * ai.x + ar.y * ai.y + ar.z * ai.z + ar.w * ai.w;

    #pragma unroll
    for (int o = 16; o; o >>= 1) {
        sr  += __shfl_xor_sync(0xffffffffu, sr,  o);
        si  += __shfl_xor_sync(0xffffffffu, si,  o);
        srr += __shfl_xor_sync(0xffffffffu, srr, o);
        sii += __shfl_xor_sync(0xffffffffu, sii, o);
        sri += __shfl_xor_sync(0xffffffffu, sri, o);
    }
    if ((tid & 31) == 0) {
        const int w = tid >> 5;
        red[0][w] = sr; red[1][w] = si; red[2][w] = srr;
        red[3][w] = sii; red[4][w] = sri;
    }
    __syncthreads();
    float Sr = 0, Si = 0, Srr = 0, Sii = 0, Sri = 0;
    #pragma unroll
    for (int i = 0; i < 8; i++) {
        Sr += red[0][i]; Si += red[1][i]; Srr += red[2][i];
        Sii += red[3][i]; Sri += red[4][i];
    }

    const float invD = 1.0f / 1024.0f;
    const float mr = Sr * invD, mi = Si * invD;
    const float vr = (Srr * invD - mr * mr) - (Sii * invD - mi * mi) + 1e-6f;
    const float vi = 2.0f * (Sri * invD - mr * mi);

    // complex sqrt (principal branch)
    const float rad = sqrtf(vr * vr + vi * vi);
    const float c  = sqrtf(fmaxf(0.5f * (rad + vr), 0.0f));
    const float dd = copysignf(sqrtf(fmaxf(0.5f * (rad - vr), 0.0f)), vi);
    const float inv = 1.0f / (c * c + dd * dd);

    const int d0 = tid * 4;
    const float4 A2 = ((const float4*)a2)[tid];
    const float4 B2 = ((const float4*)b2)[tid];

    float4 yr, yi;
    {
        float wr = ar.x - mr, wi = ai.x - mi;
        yr.x = (wr * c + wi * dd) * inv * A2.x + B2.x;
        yi.x = (wi * c - wr * dd) * inv * A2.x;
    }
    {
        float wr = ar.y - mr, wi = ai.y - mi;
        yr.y = (wr * c + wi * dd) * inv * A2.y + B2.y;
        yi.y = (wi * c - wr * dd) * inv * A2.y;
    }
    {
        float wr = ar.z - mr, wi = ai.z - mi;
        yr.z = (wr * c + wi * dd) * inv * A2.z + B2.z;
        yi.z = (wi * c - wr * dd) * inv * A2.z;
    }
    {
        float wr = ar.w - mr, wi = ai.w - mi;
        yr.w = (wr * c + wi * dd) * inv * A2.w + B2.w;
        yi.w = (wi * c - wr * dd) * inv * A2.w;
    }
    *(float4*)&out[row * 1024 + d0] = yr;
    *(float4*)&out[(size_t)PLANE + row * 1024 + d0] = yi;
}

// ---------------------------------------------------------------------------
extern "C" void kernel_launch(void* const* d_in, const int* in_sizes, int n_in,
                              void* d_out, int out_size) {
    (void)in_sizes; (void)n_in; (void)out_size;
    ProjArgs pa;
    // inputs: 0..5 = q_real,q_imag,k_real,k_imag,v_real,v_imag
    //         6..17 = Wq_r,bq_r,Wq_i,bq_i,Wk_r,bk_r,Wk_i,bk_i,Wv_r,bv_r,Wv_i,bv_i
    //         18 = a_2, 19 = b_2
    for (int i = 0; i < 6; i++) {
        pa.X[i]  = (const float*)d_in[i];
        pa.W[i]  = (const float*)d_in[6 + 2 * i];
        pa.Bv[i] = (const float*)d_in[7 + 2 * i];
    }

    proj_kernel<<<dim3(8, 128, 6), 256>>>(pa);
    scores_kernel<<<dim3(8, 8, 16), 256>>>();
    softmax_kernel<<<MTOT, 256>>>();
    av_kernel<<<dim3(8, 8, 32), 256>>>();
    lnorm_kernel<<<MTOT, 256>>>((const float*)d_in[18], (const float*)d_in[19],
                                (float*)d_out);
}

// round 3
// speedup vs baseline: 2.3322x; 2.3322x over previous
#include <cuda_runtime.h>
#include <cuda_bf16.h>
#include <cstdint>

typedef __nv_bfloat16 bf;

#define NB 16
#define SS_ 1024
#define DD_ 1024
#define MTOT (NB*SS_)              // 16384
#define PLANE (MTOT*DD_)           // 16,777,216
#define BATSTR (SS_*DD_)           // 1,048,576

// ---------------- device scratch (statics; no allocation allowed) ----------
__device__ bf g_xh[6][PLANE];      __device__ bf g_xl[6][PLANE];      // split inputs
__device__ bf g_wh[6][DD_*DD_];    __device__ bf g_wl[6][DD_*DD_];    // split weights
__device__ bf g_ph[6][PLANE];      __device__ bf g_pl[6][PLANE];      // proj outputs
__device__ bf g_th[3][PLANE];      __device__ bf g_tl[3][PLANE];      // transposed kr,vr,vi
__device__ bf g_ah[PLANE];         __device__ bf g_al[PLANE];         // split attn
__device__ float g_att[PLANE];     // raw scores
__device__ float g_or[PLANE];      __device__ float g_oi[PLANE];

// ---------------- helpers ---------------------------------------------------
__device__ __forceinline__ uint32_t smem_u32(const void* p) {
    uint32_t a;
    asm("{ .reg .u64 t; cvta.to.shared.u64 t, %1; cvt.u32.u64 %0, t; }"
        : "=r"(a) : "l"(p));
    return a;
}
__device__ __forceinline__ void cp16(uint32_t s, const void* g) {
    asm volatile("cp.async.cg.shared.global [%0], [%1], 16;" :: "r"(s), "l"(g));
}
#define CP_COMMIT() asm volatile("cp.async.commit_group;" ::: "memory")
#define CP_WAIT2()  asm volatile("cp.async.wait_group 2;" ::: "memory")
#define CP_WAIT0()  asm volatile("cp.async.wait_group 0;" ::: "memory")

__device__ __forceinline__ void ldm4(uint32_t* r, uint32_t addr) {
    asm volatile("ldmatrix.sync.aligned.m8n8.x4.shared.b16 {%0,%1,%2,%3}, [%4];"
        : "=r"(r[0]), "=r"(r[1]), "=r"(r[2]), "=r"(r[3]) : "r"(addr));
}
__device__ __forceinline__ void mma16816(float* d, const uint32_t* a, const uint32_t* b) {
    asm volatile(
        "mma.sync.aligned.m16n8k16.row.col.f32.bf16.bf16.f32 "
        "{%0,%1,%2,%3}, {%4,%5,%6,%7}, {%8,%9}, {%0,%1,%2,%3};"
        : "+f"(d[0]), "+f"(d[1]), "+f"(d[2]), "+f"(d[3])
        : "r"(a[0]), "r"(a[1]), "r"(a[2]), "r"(a[3]), "r"(b[0]), "r"(b[1]));
}

// ---------------- tensor-core split-bf16 NT GEMM ----------------------------
// C[m,n] = sum_pair sum_k A[m,k]*B[n,k], fp32 acc, 3-part bf16 split:
//   hi*hi + hi*lo + lo*hi  (error ~2^-16)
#define BM 128
#define BN 128
#define STAGES 4
#define PITCHB 80                   // 32 bf16 + 8 pad  -> 80 bytes/row
#define PART_BYTES (128*PITCHB)     // 10240
#define STG_BYTES (4*PART_BYTES)    // 40960 (Ah, Al, Bh, Bl)
#define DSM_BYTES (STAGES*STG_BYTES)

// EPI: 0 = write fp32 C ; 1 = add bias, write split bf16 hi/lo
template<int EPI>
__global__ __launch_bounds__(256, 1) void gemm_k(int job, const float* __restrict__ bias) {
    const bf *Ah[2], *Al[2], *Bh[2], *Bl[2];
    size_t bstr = 0; int npair = 1;
    float* Cf = nullptr; bf* Ch = nullptr; bf* Cl = nullptr;
    if (job < 6) {            // projections: X @ W^T + b -> split bf16
        Ah[0] = g_xh[job]; Al[0] = g_xl[job];
        Bh[0] = g_wh[job]; Bl[0] = g_wl[job];
        Ch = g_ph[job]; Cl = g_pl[job];
        Ah[1] = Ah[0]; Al[1] = Al[0]; Bh[1] = Bh[0]; Bl[1] = Bl[0];
    } else if (job == 6) {    // scores: qr@(krT)^T... = qr·krT rows + qi·ki rows
        Ah[0] = g_ph[0]; Al[0] = g_pl[0]; Bh[0] = g_th[0]; Bl[0] = g_tl[0];
        Ah[1] = g_ph[1]; Al[1] = g_pl[1]; Bh[1] = g_ph[3]; Bl[1] = g_pl[3];
        npair = 2; bstr = BATSTR; Cf = g_att;
    } else {                  // av: attn @ v^T-rows -> fp32
        int w = job - 7;
        Ah[0] = g_ah; Al[0] = g_al;
        Bh[0] = g_th[1 + w]; Bl[0] = g_tl[1 + w];
        bstr = BATSTR; Cf = w ? g_oi : g_or;
        Ah[1] = Ah[0]; Al[1] = Al[0]; Bh[1] = Bh[0]; Bl[1] = Bl[0];
    }
    const size_t zoff  = (size_t)blockIdx.z * bstr;     // element offset
    const size_t zoffb = zoff * 2;                      // byte offset
    const int m0 = blockIdx.y * BM, n0 = blockIdx.x * BN;
    const int T = npair * 32;                           // k-tiles of 32

    extern __shared__ char dsm[];
    const uint32_t base = smem_u32(dsm);
    const int tid = threadIdx.x, wid = tid >> 5, lane = tid & 31;
    const int wm = (wid >> 2) * 64;                     // warp m-offset (2 rows of warps)
    const int wn = (wid & 3) * 32;                      // warp n-offset (4 cols)

    // cp.async mapping: each thread owns 2 consecutive 16B chunks per part
    const int ld_row = tid >> 1;            // 0..127
    const int ld_col = (tid & 1) * 2;       // chunk 0/2

    auto loads = [&](int it, int s) {
        const int pr = it >> 5;             // pair (scores only)
        const int kt = it & 31;             // k-tile within 1024
        const uint32_t sb = base + s * STG_BYTES;
        const size_t ga = zoffb + ((size_t)(m0 + ld_row) * 1024 + kt * 32) * 2 + ld_col * 16;
        const size_t gb = zoffb + ((size_t)(n0 + ld_row) * 1024 + kt * 32) * 2 + ld_col * 16;
        const uint32_t so = ld_row * PITCHB + ld_col * 16;
        const char* pAh = (const char*)Ah[pr] + ga;
        const char* pAl = (const char*)Al[pr] + ga;
        const char* pBh = (const char*)Bh[pr] + gb;
        const char* pBl = (const char*)Bl[pr] + gb;
        cp16(sb + so,                    pAh);
        cp16(sb + so + 16,               pAh + 16);
        cp16(sb + PART_BYTES + so,       pAl);
        cp16(sb + PART_BYTES + so + 16,  pAl + 16);
        cp16(sb + 2*PART_BYTES + so,     pBh);
        cp16(sb + 2*PART_BYTES + so + 16, pBh + 16);
        cp16(sb + 3*PART_BYTES + so,     pBl);
        cp16(sb + 3*PART_BYTES + so + 16, pBl + 16);
    };

    // ldmatrix per-lane address components
    const int g = lane >> 3, lr = lane & 7;
    const uint32_t a_row = ((g & 1) * 8 + lr) * PITCHB;   // + mbase*80
    const uint32_t a_col = (g >> 1) * 16;                 // + kstep*32
    const uint32_t b_row = ((g >> 1) * 8 + lr) * PITCHB;  // + nbase*80
    const uint32_t b_col = (g & 1) * 16;

    float acc[4][4][4] = {};

    for (int s = 0; s < STAGES - 1; ++s) {
        if (s < T) loads(s, s);
        CP_COMMIT();
    }

    for (int it = 0; it < T; ++it) {
        CP_WAIT2();
        __syncthreads();
        if (it + STAGES - 1 < T) loads(it + STAGES - 1, (it + STAGES - 1) % STAGES);
        CP_COMMIT();

        const uint32_t sb = base + (it % STAGES) * STG_BYTES;
        #pragma unroll
        for (int ks = 0; ks < 2; ++ks) {
            uint32_t ah[4][4], al[4][4], bh4[2][4], bl4[2][4];
            const uint32_t ak = ks * 32 + a_col;
            const uint32_t bk = ks * 32 + b_col;
            #pragma unroll
            for (int mf = 0; mf < 4; ++mf) {
                const uint32_t ro = (uint32_t)(wm + mf * 16) * PITCHB + a_row + ak;
                ldm4(ah[mf], sb + ro);
                ldm4(al[mf], sb + PART_BYTES + ro);
            }
            #pragma unroll
            for (int nf2 = 0; nf2 < 2; ++nf2) {
                const uint32_t ro = (uint32_t)(wn + nf2 * 16) * PITCHB + b_row + bk;
                ldm4(bh4[nf2], sb + 2*PART_BYTES + ro);
                ldm4(bl4[nf2], sb + 3*PART_BYTES + ro);
            }
            #pragma unroll
            for (int mi = 0; mi < 4; ++mi)
                #pragma unroll
                for (int ni = 0; ni < 4; ++ni) {
                    const uint32_t* bh_f = &bh4[ni >> 1][(ni & 1) * 2];
                    const uint32_t* bl_f = &bl4[ni >> 1][(ni & 1) * 2];
                    mma16816(acc[mi][ni], ah[mi], bh_f);   // hi*hi
                    mma16816(acc[mi][ni], ah[mi], bl_f);   // hi*lo
                    mma16816(acc[mi][ni], al[mi], bh_f);   // lo*hi
                }
        }
    }
    CP_WAIT0();

    // ---------------- epilogue (register -> gmem) ----------------
    const int em = m0 + wm + (lane >> 2);
    const int en = n0 + wn + (lane & 3) * 2;
    #pragma unroll
    for (int mi = 0; mi < 4; ++mi) {
        #pragma unroll
        for (int ni = 0; ni < 4; ++ni) {
            const int m = em + mi * 16;
            const int n = en + ni * 8;
            const float* a = acc[mi][ni];
            if (EPI == 0) {
                float2 v0 = {a[0], a[1]};
                float2 v1 = {a[2], a[3]};
                *(float2*)&Cf[zoff + (size_t)m * 1024 + n]       = v0;
                *(float2*)&Cf[zoff + (size_t)(m + 8) * 1024 + n] = v1;
            } else {
                const float b0 = __ldg(&bias[n]), b1 = __ldg(&bias[n + 1]);
                #pragma unroll
                for (int rr = 0; rr < 2; ++rr) {
                    const float v0 = a[rr * 2 + 0] + b0;
                    const float v1 = a[rr * 2 + 1] + b1;
                    bf h0 = __float2bfloat16_rn(v0), h1 = __float2bfloat16_rn(v1);
                    bf l0 = __float2bfloat16_rn(v0 - __bfloat162float(h0));
                    bf l1 = __float2bfloat16_rn(v1 - __bfloat162float(h1));
                    const size_t off = (size_t)(m + rr * 8) * 1024 + n;
                    __nv_bfloat162 t;
                    t.x = h0; t.y = h1; *(__nv_bfloat162*)(Ch + off) = t;
                    t.x = l0; t.y = l1; *(__nv_bfloat162*)(Cl + off) = t;
                }
            }
        }
    }
}

// ---------------- fp32 -> (hi, lo) bf16 split -------------------------------
__global__ __launch_bounds__(256) void split_k(int job, const float4* __restrict__ src) {
    bf *h, *l; int n4;
    if (job < 6) { h = g_xh[job]; l = g_xl[job]; n4 = PLANE / 4; }
    else         { h = g_wh[job - 6]; l = g_wl[job - 6]; n4 = (DD_ * DD_) / 4; }
    const int i = blockIdx.x * 256 + threadIdx.x;
    if (i >= n4) return;
    const float4 v = src[i];
    bf h0 = __float2bfloat16_rn(v.x), h1 = __float2bfloat16_rn(v.y);
    bf h2 = __float2bfloat16_rn(v.z), h3 = __float2bfloat16_rn(v.w);
    bf l0 = __float2bfloat16_rn(v.x - __bfloat162float(h0));
    bf l1 = __float2bfloat16_rn(v.y - __bfloat162float(h1));
    bf l2 = __float2bfloat16_rn(v.z - __bfloat162float(h2));
    bf l3 = __float2bfloat16_rn(v.w - __bfloat162float(h3));
    __nv_bfloat162 t;
    t.x = h0; t.y = h1; *(__nv_bfloat162*)(h + 4 * (size_t)i)     = t;
    t.x = h2; t.y = h3; *(__nv_bfloat162*)(h + 4 * (size_t)i + 2) = t;
    t.x = l0; t.y = l1; *(__nv_bfloat162*)(l + 4 * (size_t)i)     = t;
    t.x = l2; t.y = l3; *(__nv_bfloat162*)(l + 4 * (size_t)i + 2) = t;
}

// ---------------- batched 1024x1024 bf16 transpose (kr, vr, vi hi+lo) -------
__global__ __launch_bounds__(256) void transpose_k() {
    const int z = blockIdx.z, t = z >> 4, b = z & 15;
    const int si = (t == 0) ? 2 : (t == 1 ? 4 : 5);
    const bf* sh = g_ph[si] + (size_t)b * BATSTR;
    const bf* sl = g_pl[si] + (size_t)b * BATSTR;
    bf* dh = g_th[t] + (size_t)b * BATSTR;
    bf* dl = g_tl[t] + (size_t)b * BATSTR;
    __shared__ bf Th[32][33], Tl[32][33];
    const int tx = threadIdx.x, ty = threadIdx.y;
    const int x0 = blockIdx.x * 32, y0 = blockIdx.y * 32;
    #pragma unroll
    for (int j = ty; j < 32; j += 8) {
        Th[j][tx] = sh[(size_t)(y0 + j) * 1024 + x0 + tx];
        Tl[j][tx] = sl[(size_t)(y0 + j) * 1024 + x0 + tx];
    }
    __syncthreads();
    #pragma unroll
    for (int j = ty; j < 32; j += 8) {
        dh[(size_t)(x0 + j) * 1024 + y0 + tx] = Th[tx][j];
        dl[(size_t)(x0 + j) * 1024 + y0 + tx] = Tl[tx][j];
    }
}

// ---------------- softmax (scale 0.125 folded) -> split bf16 -----------------
__global__ __launch_bounds__(256) void softmax_k() {
    __shared__ float red[8];
    const size_t rowo = (size_t)blockIdx.x * 1024;
    const float* p = g_att + rowo;
    const int tid = threadIdx.x;

    float4 v = ((const float4*)p)[tid];
    v.x *= 0.125f; v.y *= 0.125f; v.z *= 0.125f; v.w *= 0.125f;

    float m = fmaxf(fmaxf(v.x, v.y), fmaxf(v.z, v.w));
    #pragma unroll
    for (int o = 16; o; o >>= 1) m = fmaxf(m, __shfl_xor_sync(0xffffffffu, m, o));
    if ((tid & 31) == 0) red[tid >> 5] = m;
    __syncthreads();
    float M = red[0];
    #pragma unroll
    for (int i = 1; i < 8; i++) M = fmaxf(M, red[i]);
    __syncthreads();

    v.x = expf(v.x - M); v.y = expf(v.y - M);
    v.z = expf(v.z - M); v.w = expf(v.w - M);
    float s = v.x + v.y + v.z + v.w;
    #pragma unroll
    for (int o = 16; o; o >>= 1) s += __shfl_xor_sync(0xffffffffu, s, o);
    if ((tid & 31) == 0) red[tid >> 5] = s;
    __syncthreads();
    float Tt = 0.f;
    #pragma unroll
    for (int i = 0; i < 8; i++) Tt += red[i];
    const float inv = 1.0f / Tt;
    v.x *= inv; v.y *= inv; v.z *= inv; v.w *= inv;

    bf h0 = __float2bfloat16_rn(v.x), h1 = __float2bfloat16_rn(v.y);
    bf h2 = __float2bfloat16_rn(v.z), h3 = __float2bfloat16_rn(v.w);
    bf l0 = __float2bfloat16_rn(v.x - __bfloat162float(h0));
    bf l1 = __float2bfloat16_rn(v.y - __bfloat162float(h1));
    bf l2 = __float2bfloat16_rn(v.z - __bfloat162float(h2));
    bf l3 = __float2bfloat16_rn(v.w - __bfloat162float(h3));
    const size_t o4 = rowo + (size_t)tid * 4;
    __nv_bfloat162 t;
    t.x = h0; t.y = h1; *(__nv_bfloat162*)(g_ah + o4)     = t;
    t.x = h2; t.y = h3; *(__nv_bfloat162*)(g_ah + o4 + 2) = t;
    t.x = l0; t.y = l1; *(__nv_bfloat162*)(g_al + o4)     = t;
    t.x = l2; t.y = l3; *(__nv_bfloat162*)(g_al + o4 + 2) = t;
}

// ---------------- complex LayerNorm + writeback ------------------------------
__global__ __launch_bounds__(256) void lnorm_k(const float* __restrict__ a2,
                                               const float* __restrict__ b2,
                                               float* __restrict__ out) {
    __shared__ float red[5][8];
    const size_t row = blockIdx.x;
    const int tid = threadIdx.x;
    const float4 ar = ((const float4*)(g_or + row * 1024))[tid];
    const float4 ai = ((const float4*)(g_oi + row * 1024))[tid];

    float sr  = ar.x + ar.y + ar.z + ar.w;
    float si  = ai.x + ai.y + ai.z + ai.w;
    float srr = ar.x*ar.x + ar.y*ar.y + ar.z*ar.z + ar.w*ar.w;
    float sii = ai.x*ai.x + ai.y*ai.y + ai.z*ai.z + ai.w*ai.w;
    float sri = ar.x*ai.x + ar.y*ai.y + ar.z*ai.z + ar.w*ai.w;
    #pragma unroll
    for (int o = 16; o; o >>= 1) {
        sr  += __shfl_xor_sync(0xffffffffu, sr,  o);
        si  += __shfl_xor_sync(0xffffffffu, si,  o);
        srr += __shfl_xor_sync(0xffffffffu, srr, o);
        sii += __shfl_xor_sync(0xffffffffu, sii, o);
        sri += __shfl_xor_sync(0xffffffffu, sri, o);
    }
    if ((tid & 31) == 0) {
        const int w = tid >> 5;
        red[0][w] = sr; red[1][w] = si; red[2][w] = srr;
        red[3][w] = sii; red[4][w] = sri;
    }
    __syncthreads();
    float Sr = 0, Si = 0, Srr = 0, Sii = 0, Sri = 0;
    #pragma unroll
    for (int i = 0; i < 8; i++) {
        Sr += red[0][i]; Si += red[1][i]; Srr += red[2][i];
        Sii += red[3][i]; Sri += red[4][i];
    }
    const float invD = 1.0f / 1024.0f;
    const float mr = Sr * invD, mi = Si * invD;
    const float vr = (Srr * invD - mr * mr) - (Sii * invD - mi * mi) + 1e-6f;
    const float vi = 2.0f * (Sri * invD - mr * mi);
    const float rad = sqrtf(vr * vr + vi * vi);
    const float c  = sqrtf(fmaxf(0.5f * (rad + vr), 0.0f));
    const float dd = copysignf(sqrtf(fmaxf(0.5f * (rad - vr), 0.0f)), vi);
    const float inv = 1.0f / (c * c + dd * dd);

    const int d0 = tid * 4;
    const float4 A2 = ((const float4*)a2)[tid];
    const float4 B2 = ((const float4*)b2)[tid];
    float4 yr, yi;
    { float wr = ar.x - mr, wi = ai.x - mi;
      yr.x = (wr*c + wi*dd)*inv*A2.x + B2.x; yi.x = (wi*c - wr*dd)*inv*A2.x; }
    { float wr = ar.y - mr, wi = ai.y - mi;
      yr.y = (wr*c + wi*dd)*inv*A2.y + B2.y; yi.y = (wi*c - wr*dd)*inv*A2.y; }
    { float wr = ar.z - mr, wi = ai.z - mi;
      yr.z = (wr*c + wi*dd)*inv*A2.z + B2.z; yi.z = (wi*c - wr*dd)*inv*A2.z; }
    { float wr = ar.w - mr, wi = ai.w - mi;
      yr.w = (wr*c + wi*dd)*inv*A2.w + B2.w; yi.w = (wi*c - wr*dd)*inv*A2.w; }
    *(float4*)&out[row * 1024 + d0] = yr;
    *(float4*)&out[(size_t)PLANE + row * 1024 + d0] = yi;
}

// ---------------------------------------------------------------------------
extern "C" void kernel_launch(void* const* d_in, const int* in_sizes, int n_in,
                              void* d_out, int out_size) {
    (void)in_sizes; (void)n_in; (void)out_size;
    cudaFuncSetAttribute(gemm_k<0>, cudaFuncAttributeMaxDynamicSharedMemorySize, DSM_BYTES);
    cudaFuncSetAttribute(gemm_k<1>, cudaFuncAttributeMaxDynamicSharedMemorySize, DSM_BYTES);

    // split inputs + weights into bf16 hi/lo
    for (int j = 0; j < 6; j++)
        split_k<<<PLANE / 4 / 256, 256>>>(j, (const float4*)d_in[j]);
    for (int j = 0; j < 6; j++)
        split_k<<<(DD_ * DD_) / 4 / 256, 256>>>(6 + j, (const float4*)d_in[6 + 2 * j]);

    // 6 projections (X @ W^T + b) -> split bf16
    for (int j = 0; j < 6; j++)
        gemm_k<1><<<dim3(8, 128, 1), 256, DSM_BYTES>>>(j, (const float*)d_in[7 + 2 * j]);

    // transpose kr, vr, vi (hi+lo) per batch
    transpose_k<<<dim3(32, 32, 48), dim3(32, 8)>>>();

    // scores = qr@krT + qi@ki^T  (fp32)
    gemm_k<0><<<dim3(8, 8, 16), 256, DSM_BYTES>>>(6, nullptr);

    // softmax (+0.125 scale) -> split bf16 attn
    softmax_k<<<MTOT, 256>>>();

    // out_r = attn@vr, out_i = attn@vi
    gemm_k<0><<<dim3(8, 8, 16), 256, DSM_BYTES>>>(7, nullptr);
    gemm_k<0><<<dim3(8, 8, 16), 256, DSM_BYTES>>>(8, nullptr);

    // complex LayerNorm -> [2,B,S,D]
    lnorm_k<<<MTOT, 256>>>((const float*)d_in[18], (const float*)d_in[19], (float*)d_out);
}